// round 1
// baseline (speedup 1.0000x reference)
#include <cuda_runtime.h>

// Cross-attention: B=8, N=M=2048, D=1024, fp32.
//   q = query @ Wq^T + bq ; k,v likewise from context
//   s = (q k^T)/sqrt(D), mask==0 -> -1e9, softmax over M
//   out = s @ v
//
// Round 1 baseline: fp32 register-blocked SGEMM (128x128x8, 8x8/thread),
// fused scale+mask+softmax, device-global scratch (no allocations).

#define BM 128
#define BN 128
#define BK 8

// Scratch (device globals: allowed; harness forbids runtime allocation).
__device__ float g_q[8 * 2048 * 1024];
__device__ float g_k[8 * 2048 * 1024];
__device__ float g_v[8 * 2048 * 1024];
__device__ float g_s[8 * 2048 * 2048];   // scores -> probs (in place)

// Generic batched GEMM:  C[M,N] = A[M,K] * op(B) (+ bias)
//   TRANSB=true : B is [N,K] row-major (dot of rows; used for X@W^T and Q@K^T)
//   TRANSB=false: B is [K,N] row-major (used for P@V)
// blockIdx.z = batch, with element strides sA/sB/sC.
template <bool TRANSB, bool BIAS>
__global__ __launch_bounds__(256, 2)
void gemm_kernel(const float* __restrict__ Ag, const float* __restrict__ Bg,
                 const float* __restrict__ bias, float* __restrict__ Cg,
                 int M, int N, int K,
                 long long sA, long long sB, long long sC)
{
    __shared__ float As[BK][BM];
    __shared__ float Bs[BK][BN];

    const float* A  = Ag + (long long)blockIdx.z * sA;
    const float* Bp = Bg + (long long)blockIdx.z * sB;
    float*       C  = Cg + (long long)blockIdx.z * sC;

    const int tid = threadIdx.x;
    const int m0 = blockIdx.y * BM;
    const int n0 = blockIdx.x * BN;

    // loader indices (K-contiguous tiles, float4)
    const int lRow = tid >> 1;          // 0..127
    const int lCol = (tid & 1) * 4;     // 0 or 4
    // NN loader indices
    const int bRow = tid >> 5;          // 0..7  (k within tile)
    const int bCol = tid & 31;          // 0..31 (n, strided by 32)

    const int tx = tid & 15;            // 16x16 thread tile
    const int ty = tid >> 4;

    float acc[8][8];
#pragma unroll
    for (int i = 0; i < 8; ++i)
#pragma unroll
        for (int j = 0; j < 8; ++j) acc[i][j] = 0.f;

    for (int k0 = 0; k0 < K; k0 += BK) {
        // A tile: As[k][m]
        float4 av = *reinterpret_cast<const float4*>(
            A + (long long)(m0 + lRow) * K + k0 + lCol);
        As[lCol + 0][lRow] = av.x;
        As[lCol + 1][lRow] = av.y;
        As[lCol + 2][lRow] = av.z;
        As[lCol + 3][lRow] = av.w;

        if (TRANSB) {
            // B[N,K] row-major: Bs[k][n]
            float4 bv = *reinterpret_cast<const float4*>(
                Bp + (long long)(n0 + lRow) * K + k0 + lCol);
            Bs[lCol + 0][lRow] = bv.x;
            Bs[lCol + 1][lRow] = bv.y;
            Bs[lCol + 2][lRow] = bv.z;
            Bs[lCol + 3][lRow] = bv.w;
        } else {
            // B[K,N] row-major: coalesced rows
#pragma unroll
            for (int j = 0; j < 4; ++j)
                Bs[bRow][bCol + 32 * j] =
                    Bp[(long long)(k0 + bRow) * N + n0 + bCol + 32 * j];
        }
        __syncthreads();

#pragma unroll
        for (int kk = 0; kk < BK; ++kk) {
            float a[8], b[8];
            *reinterpret_cast<float4*>(&a[0]) =
                *reinterpret_cast<const float4*>(&As[kk][ty * 4]);
            *reinterpret_cast<float4*>(&a[4]) =
                *reinterpret_cast<const float4*>(&As[kk][64 + ty * 4]);
            *reinterpret_cast<float4*>(&b[0]) =
                *reinterpret_cast<const float4*>(&Bs[kk][tx * 4]);
            *reinterpret_cast<float4*>(&b[4]) =
                *reinterpret_cast<const float4*>(&Bs[kk][64 + tx * 4]);
#pragma unroll
            for (int i = 0; i < 8; ++i)
#pragma unroll
                for (int j = 0; j < 8; ++j)
                    acc[i][j] = fmaf(a[i], b[j], acc[i][j]);
        }
        __syncthreads();
    }

    // epilogue: 2x2 blocks of 4x4, float4 stores, optional bias
#pragma unroll
    for (int ih = 0; ih < 2; ++ih) {
#pragma unroll
        for (int i = 0; i < 4; ++i) {
            const int row = m0 + ih * 64 + ty * 4 + i;
#pragma unroll
            for (int jh = 0; jh < 2; ++jh) {
                const int col = n0 + jh * 64 + tx * 4;
                float4 r;
                r.x = acc[ih * 4 + i][jh * 4 + 0];
                r.y = acc[ih * 4 + i][jh * 4 + 1];
                r.z = acc[ih * 4 + i][jh * 4 + 2];
                r.w = acc[ih * 4 + i][jh * 4 + 3];
                if (BIAS) {
                    r.x += bias[col + 0];
                    r.y += bias[col + 1];
                    r.z += bias[col + 2];
                    r.w += bias[col + 3];
                }
                *reinterpret_cast<float4*>(C + (long long)row * N + col) = r;
            }
        }
    }
}

// Fused scale + mask + softmax over one row of 2048 scores (in place).
__global__ __launch_bounds__(256)
void softmax_kernel(float* __restrict__ S, const int* __restrict__ mask)
{
    const int row = blockIdx.x;          // b*2048 + n
    const int b = row >> 11;
    float* s = S + (long long)row * 2048;
    const int* mk = mask + b * 2048;
    const int tid = threadIdx.x;

    const float scale = 0.03125f;        // 1/sqrt(1024)

    float v[8];
    float lmax = -3.0e38f;
#pragma unroll
    for (int j = 0; j < 8; ++j) {
        const int m = tid + j * 256;
        float x = s[m] * scale;
        if (mk[m] == 0) x = -1e9f;
        v[j] = x;
        lmax = fmaxf(lmax, x);
    }

    __shared__ float red[32];
#pragma unroll
    for (int o = 16; o; o >>= 1)
        lmax = fmaxf(lmax, __shfl_xor_sync(0xffffffffu, lmax, o));
    if ((tid & 31) == 0) red[tid >> 5] = lmax;
    __syncthreads();
    const float rmax = fmaxf(fmaxf(fmaxf(red[0], red[1]), fmaxf(red[2], red[3])),
                             fmaxf(fmaxf(red[4], red[5]), fmaxf(red[6], red[7])));
    __syncthreads();   // red reused below

    float lsum = 0.f;
#pragma unroll
    for (int j = 0; j < 8; ++j) {
        v[j] = expf(v[j] - rmax);
        lsum += v[j];
    }
#pragma unroll
    for (int o = 16; o; o >>= 1)
        lsum += __shfl_xor_sync(0xffffffffu, lsum, o);
    if ((tid & 31) == 0) red[tid >> 5] = lsum;
    __syncthreads();
    const float rsum = red[0] + red[1] + red[2] + red[3] +
                       red[4] + red[5] + red[6] + red[7];
    const float inv = 1.f / rsum;
#pragma unroll
    for (int j = 0; j < 8; ++j)
        s[tid + j * 256] = v[j] * inv;
}

extern "C" void kernel_launch(void* const* d_in, const int* in_sizes, int n_in,
                              void* d_out, int out_size)
{
    const float* query   = (const float*)d_in[0];
    const float* context = (const float*)d_in[1];
    const int*   cmask   = (const int*)  d_in[2];
    const float* Wq = (const float*)d_in[3];
    const float* bq = (const float*)d_in[4];
    const float* Wk = (const float*)d_in[5];
    const float* bk = (const float*)d_in[6];
    const float* Wv = (const float*)d_in[7];
    const float* bv = (const float*)d_in[8];
    float* out = (float*)d_out;

    float *q, *k, *v, *s;
    cudaGetSymbolAddress((void**)&q, g_q);
    cudaGetSymbolAddress((void**)&k, g_k);
    cudaGetSymbolAddress((void**)&v, g_v);
    cudaGetSymbolAddress((void**)&s, g_s);

    dim3 blk(256);

    // Projections: [16384,1024] = [16384,1024] @ W^T + b   (NT, bias)
    dim3 gProj(1024 / BN, 16384 / BM, 1);
    gemm_kernel<true, true><<<gProj, blk>>>(query,   Wq, bq, q, 16384, 1024, 1024, 0, 0, 0);
    gemm_kernel<true, true><<<gProj, blk>>>(context, Wk, bk, k, 16384, 1024, 1024, 0, 0, 0);
    gemm_kernel<true, true><<<gProj, blk>>>(context, Wv, bv, v, 16384, 1024, 1024, 0, 0, 0);

    // Scores: per batch [2048,2048] = Q @ K^T   (NT)
    dim3 gS(2048 / BN, 2048 / BM, 8);
    gemm_kernel<true, false><<<gS, blk>>>(q, k, nullptr, s, 2048, 2048, 1024,
                                          2048ll * 1024, 2048ll * 1024, 2048ll * 2048);

    // scale + mask + softmax, in place
    softmax_kernel<<<16384, 256>>>(s, cmask);

    // Out: per batch [2048,1024] = P @ V   (NN)
    dim3 gO(1024 / BN, 2048 / BM, 8);
    gemm_kernel<false, false><<<gO, blk>>>(s, v, nullptr, out, 2048, 1024, 2048,
                                           2048ll * 2048, 2048ll * 1024, 2048ll * 1024);
}

// round 4
// speedup vs baseline: 2.6836x; 2.6836x over previous
#include <cuda_runtime.h>
#include <cuda_bf16.h>
#include <cstdint>

// ============================================================================
// Cross-attention, compensated-bf16 via warp-level mma.sync (HMMA, sm_80+ ISA;
// the harness targets plain sm_100 so tcgen05 is unavailable).
//   All GEMMs are bf16 NT GEMMs with K tripled:
//     A' = [a_hi, a_lo, a_hi] per k;  B' = [b_hi, b_hi, b_lo] per k
//   accumulating a_hi*b_hi + a_lo*b_hi + a_hi*b_lo in fp32 (~2^-16 operand
//   precision). Shapes: B=8, N=M=2048, D=1024. K'=3072 (proj/QK), 6144 (PV).
// ============================================================================

// ---------------- helpers ----------------
__device__ __forceinline__ uint32_t smem_u32(const void* p) {
    uint32_t a;
    asm("{ .reg .u64 t; cvta.to.shared.u64 t, %1; cvt.u32.u64 %0, t; }"
        : "=r"(a) : "l"(p));
    return a;
}
__device__ __forceinline__ void cp16(uint32_t dst, const void* src) {
    asm volatile("cp.async.cg.shared.global [%0], [%1], 16;"
                 :: "r"(dst), "l"(__cvta_generic_to_global(src)));
}
#define CP_COMMIT() asm volatile("cp.async.commit_group;" ::: "memory")
#define CP_WAIT(n)  asm volatile("cp.async.wait_group %0;" :: "n"(n) : "memory")

__device__ __forceinline__ void ldsm4(uint32_t& r0, uint32_t& r1, uint32_t& r2,
                                      uint32_t& r3, uint32_t addr) {
    asm volatile("ldmatrix.sync.aligned.m8n8.x4.shared.b16 {%0,%1,%2,%3}, [%4];"
                 : "=r"(r0), "=r"(r1), "=r"(r2), "=r"(r3) : "r"(addr));
}
__device__ __forceinline__ void mma16816(float* c, const uint32_t* a,
                                         uint32_t b0, uint32_t b1) {
    asm volatile(
        "mma.sync.aligned.m16n8k16.row.col.f32.bf16.bf16.f32 "
        "{%0,%1,%2,%3}, {%4,%5,%6,%7}, {%8,%9}, {%0,%1,%2,%3};"
        : "+f"(c[0]), "+f"(c[1]), "+f"(c[2]), "+f"(c[3])
        : "r"(a[0]), "r"(a[1]), "r"(a[2]), "r"(a[3]), "r"(b0), "r"(b1));
}
// swizzled byte offset within a tile of 128B rows (SW128)
__device__ __forceinline__ uint32_t swz(int row, int c16) {
    return (uint32_t)(row * 128 + ((c16 ^ (row & 7)) * 16));
}

// ---------------- scratch (device globals; no runtime allocation) ----------
__device__ __nv_bfloat16 g_xq[16384ull * 3072];   // query triplets (A)
__device__ __nv_bfloat16 g_xc[16384ull * 3072];   // context triplets (A)
__device__ __nv_bfloat16 g_w0[1024ull * 3072];    // Wq triplets (B)
__device__ __nv_bfloat16 g_w1[1024ull * 3072];    // Wk triplets (B)
__device__ __nv_bfloat16 g_w2[1024ull * 3072];    // Wv triplets (B)
__device__ __nv_bfloat16 g_qt[16384ull * 3072];   // q triplets (A of QK)
__device__ __nv_bfloat16 g_kt[16384ull * 3072];   // k triplets (B of QK)
__device__ __nv_bfloat16 g_vt[8ull * 1024 * 6144];// v^T triplets (B of PV)
__device__ float         g_s [16384ull * 2048];   // scores fp32
__device__ __nv_bfloat16 g_p [16384ull * 6144];   // prob triplets (A of PV)

__device__ __forceinline__ void split_us(float x, unsigned short& h, unsigned short& l) {
    __nv_bfloat16 hb = __float2bfloat16(x);
    __nv_bfloat16 lb = __float2bfloat16(x - __bfloat162float(hb));
    h = __bfloat16_as_ushort(hb);
    l = __bfloat16_as_ushort(lb);
}

// ---------------- input split kernels ----------------
// ORD=0 -> (hi,lo,hi) [A operand]; ORD=1 -> (hi,hi,lo) [B operand]
template <int ORD>
__global__ __launch_bounds__(256)
void split_kernel(const float* __restrict__ in, __nv_bfloat16* __restrict__ out)
{
    const size_t idx = (size_t)blockIdx.x * 256 + threadIdx.x;  // float4 index
    const float4 v = reinterpret_cast<const float4*>(in)[idx];
    unsigned short h[4], l[4];
    split_us(v.x, h[0], l[0]); split_us(v.y, h[1], l[1]);
    split_us(v.z, h[2], l[2]); split_us(v.w, h[3], l[3]);
    uint32_t w[6];
    if (ORD == 0) {
        w[0] = h[0] | ((uint32_t)l[0] << 16); w[1] = h[0] | ((uint32_t)h[1] << 16);
        w[2] = l[1] | ((uint32_t)h[1] << 16); w[3] = h[2] | ((uint32_t)l[2] << 16);
        w[4] = h[2] | ((uint32_t)h[3] << 16); w[5] = l[3] | ((uint32_t)h[3] << 16);
    } else {
        w[0] = h[0] | ((uint32_t)h[0] << 16); w[1] = l[0] | ((uint32_t)h[1] << 16);
        w[2] = h[1] | ((uint32_t)l[1] << 16); w[3] = h[2] | ((uint32_t)h[2] << 16);
        w[4] = l[2] | ((uint32_t)h[3] << 16); w[5] = h[3] | ((uint32_t)l[3] << 16);
    }
    uint2* o = reinterpret_cast<uint2*>(out + 12 * idx);
    o[0] = make_uint2(w[0], w[1]);
    o[1] = make_uint2(w[2], w[3]);
    o[2] = make_uint2(w[4], w[5]);
}

// ---------------- HMMA GEMM: 128x128 tile, NT, BK=64, double-buffered ------
// EPI: 0 = plain fp32 out (scores / final out)
//      1 = bias + triplet (hi,lo,hi)  [q]
//      2 = bias + triplet (hi,hi,lo)  [k]
//      3 = bias + transposed triplet (hi,hi,lo) into vt[b][n][3m]  [v]
template <int EPI>
__global__ __launch_bounds__(256, 2)
void mm_bf16(const __nv_bfloat16* __restrict__ Ag, const __nv_bfloat16* __restrict__ Bg,
             const float* __restrict__ bias, void* __restrict__ Cg,
             int M, int N, int Kp, long long sA, long long sB, long long sC)
{
    extern __shared__ char sm[];
    const uint32_t sbase = smem_u32(sm);

    const int tid = threadIdx.x, wid = tid >> 5, lane = tid & 31;
    const int m0 = blockIdx.y * 128, n0 = blockIdx.x * 128;
    const __nv_bfloat16* A = Ag + (size_t)blockIdx.z * sA;
    const __nv_bfloat16* B = Bg + (size_t)blockIdx.z * sB;

    const int lrow = tid >> 3;      // 0..31 (+32 per step)
    const int lcol = tid & 7;       // 16B chunk

    // stage s occupies [s*32768, s*32768+16384) for A, +16384 for B
    auto load_stage = [&](int i) {
        const uint32_t abase = sbase + (i & 1) * 32768;
        const uint32_t bbase = abase + 16384;
        const int k0 = i << 6;      // bf16 elements
#pragma unroll
        for (int t = 0; t < 4; ++t) {
            const int row = lrow + t * 32;
            cp16(abase + swz(row, lcol), A + (size_t)(m0 + row) * Kp + k0 + lcol * 8);
        }
#pragma unroll
        for (int t = 0; t < 4; ++t) {
            const int row = lrow + t * 32;
            cp16(bbase + swz(row, lcol), B + (size_t)(n0 + row) * Kp + k0 + lcol * 8);
        }
        CP_COMMIT();
    };

    float acc[4][4][4];
#pragma unroll
    for (int a = 0; a < 4; ++a)
#pragma unroll
        for (int b = 0; b < 4; ++b)
#pragma unroll
            for (int c = 0; c < 4; ++c) acc[a][b][c] = 0.f;

    const int wm = wid >> 2, wn = wid & 3;     // 2 x 4 warp grid, 64x32 tiles
    const int nk = Kp >> 6;

    load_stage(0);
    for (int i = 0; i < nk; ++i) {
        if (i + 1 < nk) { load_stage(i + 1); CP_WAIT(1); }
        else           { CP_WAIT(0); }
        __syncthreads();
        const uint32_t abase = sbase + (i & 1) * 32768;
        const uint32_t bbase = abase + 16384;
#pragma unroll
        for (int ks = 0; ks < 4; ++ks) {
            uint32_t af[4][4];
#pragma unroll
            for (int mi = 0; mi < 4; ++mi) {
                const int row = wm * 64 + mi * 16 + (lane & 15);
                const int c16 = ks * 2 + (lane >> 4);
                ldsm4(af[mi][0], af[mi][1], af[mi][2], af[mi][3], abase + swz(row, c16));
            }
            uint32_t bfr[4][2];
#pragma unroll
            for (int nb = 0; nb < 2; ++nb) {
                const int row = wn * 32 + nb * 16 + (lane & 7) + ((lane & 16) >> 1);
                const int c16 = ks * 2 + ((lane >> 3) & 1);
                uint32_t r0, r1, r2, r3;
                ldsm4(r0, r1, r2, r3, bbase + swz(row, c16));
                bfr[nb * 2][0] = r0; bfr[nb * 2][1] = r1;
                bfr[nb * 2 + 1][0] = r2; bfr[nb * 2 + 1][1] = r3;
            }
#pragma unroll
            for (int mi = 0; mi < 4; ++mi)
#pragma unroll
                for (int ni = 0; ni < 4; ++ni)
                    mma16816(acc[mi][ni], af[mi], bfr[ni][0], bfr[ni][1]);
        }
        __syncthreads();
    }

    // ---------------- epilogue ----------------
    const int l4 = lane >> 2;          // row within m8
    const int lc = (lane & 3) * 2;     // even col within n8
#pragma unroll
    for (int mi = 0; mi < 4; ++mi) {
#pragma unroll
        for (int h = 0; h < 2; ++h) {
            const int row = m0 + wm * 64 + mi * 16 + l4 + h * 8;
#pragma unroll
            for (int ni = 0; ni < 4; ++ni) {
                const int n = n0 + wn * 32 + ni * 8 + lc;
                const float v0 = acc[mi][ni][h * 2 + 0];
                const float v1 = acc[mi][ni][h * 2 + 1];
                if (EPI == 0) {
                    float* C = (float*)Cg + (size_t)blockIdx.z * sC + (size_t)row * N + n;
                    *reinterpret_cast<float2*>(C) = make_float2(v0, v1);
                } else if (EPI == 1 || EPI == 2) {
                    const float x0 = v0 + bias[n];
                    const float x1 = v1 + bias[n + 1];
                    unsigned short h0, l0, h1, l1;
                    split_us(x0, h0, l0); split_us(x1, h1, l1);
                    uint32_t w0, w1, w2;
                    if (EPI == 1) {          // (hi,lo,hi)
                        w0 = h0 | ((uint32_t)l0 << 16);
                        w1 = h0 | ((uint32_t)h1 << 16);
                        w2 = l1 | ((uint32_t)h1 << 16);
                    } else {                 // (hi,hi,lo)
                        w0 = h0 | ((uint32_t)h0 << 16);
                        w1 = l0 | ((uint32_t)h1 << 16);
                        w2 = h1 | ((uint32_t)l1 << 16);
                    }
                    uint32_t* p = reinterpret_cast<uint32_t*>(
                        (__nv_bfloat16*)Cg + (size_t)row * (size_t)(3 * N) + 3 * (size_t)n);
                    p[0] = w0; p[1] = w1; p[2] = w2;
                } else {                     // EPI==3: v transpose, (hi,hi,lo)
                    const int bb = row >> 11, mg = row & 2047;
#pragma unroll
                    for (int e = 0; e < 2; ++e) {
                        const int nn = n + e;
                        const float x = (e ? v1 : v0) + bias[nn];
                        unsigned short hh, ll;
                        split_us(x, hh, ll);
                        __nv_bfloat16* p = (__nv_bfloat16*)Cg +
                            ((size_t)(bb * 1024 + nn)) * 6144 + 3 * (size_t)mg;
                        p[0] = __ushort_as_bfloat16(hh);
                        p[1] = __ushort_as_bfloat16(hh);
                        p[2] = __ushort_as_bfloat16(ll);
                    }
                }
            }
        }
    }
}

// ---------------- fused scale + mask + softmax + triplet split -------------
__global__ __launch_bounds__(256)
void softmax_kernel(const float* __restrict__ S, const int* __restrict__ mask,
                    __nv_bfloat16* __restrict__ P)
{
    const int row = blockIdx.x;          // b*2048 + n
    const int b = row >> 11;
    const float* s = S + (size_t)row * 2048;
    const int* mk = mask + b * 2048;
    const int tid = threadIdx.x;
    const float scale = 0.03125f;        // 1/sqrt(1024)

    float v[8];
    float lmax = -3.0e38f;
#pragma unroll
    for (int j = 0; j < 8; ++j) {
        const int m = tid + j * 256;
        float x = s[m] * scale;
        if (mk[m] == 0) x = -1e9f;
        v[j] = x;
        lmax = fmaxf(lmax, x);
    }
    __shared__ float red[8];
#pragma unroll
    for (int o = 16; o; o >>= 1)
        lmax = fmaxf(lmax, __shfl_xor_sync(0xffffffffu, lmax, o));
    if ((tid & 31) == 0) red[tid >> 5] = lmax;
    __syncthreads();
    const float rmax = fmaxf(fmaxf(fmaxf(red[0], red[1]), fmaxf(red[2], red[3])),
                             fmaxf(fmaxf(red[4], red[5]), fmaxf(red[6], red[7])));
    __syncthreads();

    float lsum = 0.f;
#pragma unroll
    for (int j = 0; j < 8; ++j) { v[j] = expf(v[j] - rmax); lsum += v[j]; }
#pragma unroll
    for (int o = 16; o; o >>= 1)
        lsum += __shfl_xor_sync(0xffffffffu, lsum, o);
    if ((tid & 31) == 0) red[tid >> 5] = lsum;
    __syncthreads();
    const float inv = 1.f / (red[0] + red[1] + red[2] + red[3] +
                             red[4] + red[5] + red[6] + red[7]);

    __nv_bfloat16* op = P + (size_t)row * 6144;
#pragma unroll
    for (int j = 0; j < 8; ++j) {
        const int m = tid + j * 256;
        const float p = v[j] * inv;
        unsigned short h, l;
        split_us(p, h, l);
        __nv_bfloat16* q = op + 3 * m;   // (hi,lo,hi)
        q[0] = __ushort_as_bfloat16(h);
        q[1] = __ushort_as_bfloat16(l);
        q[2] = __ushort_as_bfloat16(h);
    }
}

// ---------------- launch ----------------
static constexpr size_t SMEM_BYTES = 2 * 32768;   // 2 stages x (16KB A + 16KB B)

extern "C" void kernel_launch(void* const* d_in, const int* in_sizes, int n_in,
                              void* d_out, int out_size)
{
    const float* query   = (const float*)d_in[0];
    const float* context = (const float*)d_in[1];
    const int*   cmask   = (const int*)  d_in[2];
    const float* Wq = (const float*)d_in[3];
    const float* bq = (const float*)d_in[4];
    const float* Wk = (const float*)d_in[5];
    const float* bk = (const float*)d_in[6];
    const float* Wv = (const float*)d_in[7];
    const float* bv = (const float*)d_in[8];
    float* out = (float*)d_out;

    __nv_bfloat16 *xq, *xc, *w0, *w1, *w2, *qt, *kt, *vt, *pp;
    float* s;
    cudaGetSymbolAddress((void**)&xq, g_xq);
    cudaGetSymbolAddress((void**)&xc, g_xc);
    cudaGetSymbolAddress((void**)&w0, g_w0);
    cudaGetSymbolAddress((void**)&w1, g_w1);
    cudaGetSymbolAddress((void**)&w2, g_w2);
    cudaGetSymbolAddress((void**)&qt, g_qt);
    cudaGetSymbolAddress((void**)&kt, g_kt);
    cudaGetSymbolAddress((void**)&vt, g_vt);
    cudaGetSymbolAddress((void**)&s,  g_s);
    cudaGetSymbolAddress((void**)&pp, g_p);

    cudaFuncSetAttribute(mm_bf16<0>, cudaFuncAttributeMaxDynamicSharedMemorySize, SMEM_BYTES);
    cudaFuncSetAttribute(mm_bf16<1>, cudaFuncAttributeMaxDynamicSharedMemorySize, SMEM_BYTES);
    cudaFuncSetAttribute(mm_bf16<2>, cudaFuncAttributeMaxDynamicSharedMemorySize, SMEM_BYTES);
    cudaFuncSetAttribute(mm_bf16<3>, cudaFuncAttributeMaxDynamicSharedMemorySize, SMEM_BYTES);

    // split inputs into bf16 triplets
    split_kernel<0><<<16384, 256>>>(query,   xq);
    split_kernel<0><<<16384, 256>>>(context, xc);
    split_kernel<1><<<1024,  256>>>(Wq, w0);
    split_kernel<1><<<1024,  256>>>(Wk, w1);
    split_kernel<1><<<1024,  256>>>(Wv, w2);

    // projections: [16384,1024] = X' @ W'^T + b  (K'=3072)
    mm_bf16<1><<<dim3(8, 128, 1), 256, SMEM_BYTES>>>(xq, w0, bq, qt, 16384, 1024, 3072, 0, 0, 0);
    mm_bf16<2><<<dim3(8, 128, 1), 256, SMEM_BYTES>>>(xc, w1, bk, kt, 16384, 1024, 3072, 0, 0, 0);
    mm_bf16<3><<<dim3(8, 128, 1), 256, SMEM_BYTES>>>(xc, w2, bv, vt, 16384, 1024, 3072, 0, 0, 0);

    // scores: per batch [2048,2048] = q' @ k'^T  (K'=3072)
    mm_bf16<0><<<dim3(16, 16, 8), 256, SMEM_BYTES>>>(qt, kt, nullptr, s, 2048, 2048, 3072,
                                                     2048ll * 3072, 2048ll * 3072, 2048ll * 2048);

    // softmax + prob triplet split
    softmax_kernel<<<16384, 256>>>(s, cmask, pp);

    // out: per batch [2048,1024] = P' @ vt'^T  (K'=6144)
    mm_bf16<0><<<dim3(8, 16, 8), 256, SMEM_BYTES>>>(pp, vt, nullptr, out, 2048, 1024, 6144,
                                                    2048ll * 6144, 1024ll * 6144, 2048ll * 1024);
}

// round 6
// speedup vs baseline: 4.2606x; 1.5876x over previous
#include <cuda_runtime.h>
#include <cuda_bf16.h>
#include <cstdint>

// ============================================================================
// Cross-attention, compensated-bf16 via warp-level mma.sync (HMMA, sm_80+ ISA)
// with mask-compaction: masked context columns (~50%) are removed BEFORE the
// K/V projections, the QK^T scores, and the PV matmul.
//   All GEMMs are bf16 NT GEMMs with K tripled:
//     A' = [a_hi, a_lo, a_hi] per k;  B' = [b_hi, b_hi, b_lo] per k
//   accumulating a_hi*b_hi + a_lo*b_hi + a_hi*b_lo in fp32 (~2^-16 operand
//   precision). Shapes: B=8, N=M=2048, D=1024.
// ============================================================================

// ---------------- helpers ----------------
__device__ __forceinline__ uint32_t smem_u32(const void* p) {
    uint32_t a;
    asm("{ .reg .u64 t; cvta.to.shared.u64 t, %1; cvt.u32.u64 %0, t; }"
        : "=r"(a) : "l"(p));
    return a;
}
__device__ __forceinline__ void cp16(uint32_t dst, const void* src) {
    asm volatile("cp.async.cg.shared.global [%0], [%1], 16;"
                 :: "r"(dst), "l"(__cvta_generic_to_global(src)));
}
#define CP_COMMIT() asm volatile("cp.async.commit_group;" ::: "memory")
#define CP_WAIT(n)  asm volatile("cp.async.wait_group %0;" :: "n"(n) : "memory")

__device__ __forceinline__ void ldsm4(uint32_t& r0, uint32_t& r1, uint32_t& r2,
                                      uint32_t& r3, uint32_t addr) {
    asm volatile("ldmatrix.sync.aligned.m8n8.x4.shared.b16 {%0,%1,%2,%3}, [%4];"
                 : "=r"(r0), "=r"(r1), "=r"(r2), "=r"(r3) : "r"(addr));
}
__device__ __forceinline__ void mma16816(float* c, const uint32_t* a,
                                         uint32_t b0, uint32_t b1) {
    asm volatile(
        "mma.sync.aligned.m16n8k16.row.col.f32.bf16.bf16.f32 "
        "{%0,%1,%2,%3}, {%4,%5,%6,%7}, {%8,%9}, {%0,%1,%2,%3};"
        : "+f"(c[0]), "+f"(c[1]), "+f"(c[2]), "+f"(c[3])
        : "r"(a[0]), "r"(a[1]), "r"(a[2]), "r"(a[3]), "r"(b0), "r"(b1));
}
// swizzled byte offset within a tile of 128B rows (SW128)
__device__ __forceinline__ uint32_t swz(int row, int c16) {
    return (uint32_t)(row * 128 + ((c16 ^ (row & 7)) * 16));
}

// ---------------- scratch (device globals; no runtime allocation) ----------
__device__ __nv_bfloat16 g_xq[16384ull * 3072];   // query triplets (A)
__device__ __nv_bfloat16 g_xc[16384ull * 3072];   // compacted context triplets
__device__ __nv_bfloat16 g_w0[1024ull * 3072];    // Wq triplets (B)
__device__ __nv_bfloat16 g_w1[1024ull * 3072];    // Wk triplets (B)
__device__ __nv_bfloat16 g_w2[1024ull * 3072];    // Wv triplets (B)
__device__ __nv_bfloat16 g_qt[16384ull * 3072];   // q triplets (A of QK)
__device__ __nv_bfloat16 g_kt[16384ull * 3072];   // compacted k triplets (B of QK)
__device__ __nv_bfloat16 g_vt[8ull * 1024 * 6144];// compacted v^T triplets (B of PV)
__device__ float         g_s [16384ull * 2048];   // scores fp32 (compacted cols)
__device__ __nv_bfloat16 g_p [16384ull * 6144];   // prob triplets (A of PV)
__device__ int           g_cnt[8];                // kept columns per batch
__device__ int           g_map[16384];            // compacted idx -> src row

__device__ __forceinline__ void split_us(float x, unsigned short& h, unsigned short& l) {
    __nv_bfloat16 hb = __float2bfloat16(x);
    __nv_bfloat16 lb = __float2bfloat16(x - __bfloat162float(hb));
    h = __bfloat16_as_ushort(hb);
    l = __bfloat16_as_ushort(lb);
}

// pack 4 floats into A-order (hi,lo,hi) triplets = 6 uint32
__device__ __forceinline__ void pack_a(const float4& v, uint32_t* w) {
    unsigned short h[4], l[4];
    split_us(v.x, h[0], l[0]); split_us(v.y, h[1], l[1]);
    split_us(v.z, h[2], l[2]); split_us(v.w, h[3], l[3]);
    w[0] = h[0] | ((uint32_t)l[0] << 16); w[1] = h[0] | ((uint32_t)h[1] << 16);
    w[2] = l[1] | ((uint32_t)h[1] << 16); w[3] = h[2] | ((uint32_t)l[2] << 16);
    w[4] = h[2] | ((uint32_t)h[3] << 16); w[5] = l[3] | ((uint32_t)h[3] << 16);
}

// ---------------- mask scan: per-batch compaction map ----------------
__global__ __launch_bounds__(256)
void scan_mask(const int* __restrict__ mask, int* __restrict__ map,
               int* __restrict__ count)
{
    const int b = blockIdx.x, tid = threadIdx.x;
    const int* mk = mask + b * 2048;
    int loc[8], s = 0;
#pragma unroll
    for (int e = 0; e < 8; ++e) { loc[e] = mk[tid * 8 + e]; s += loc[e]; }
    const int lane = tid & 31, w = tid >> 5;
    int ps = s;
#pragma unroll
    for (int o = 1; o < 32; o <<= 1) {
        int t = __shfl_up_sync(0xffffffffu, ps, o);
        if (lane >= o) ps += t;
    }
    __shared__ int wsum[8];
    if (lane == 31) wsum[w] = ps;
    __syncthreads();
    int woff = 0;
#pragma unroll
    for (int i = 0; i < 8; ++i) if (i < w) woff += wsum[i];
    int c = woff + ps - s;            // exclusive prefix
#pragma unroll
    for (int e = 0; e < 8; ++e)
        if (loc[e]) map[b * 2048 + (c++)] = tid * 8 + e;
    if (tid == 255) count[b] = c;
}

// ---------------- input split kernels ----------------
// ORD=0 -> (hi,lo,hi) [A operand]; ORD=1 -> (hi,hi,lo) [B operand]
template <int ORD>
__global__ __launch_bounds__(256)
void split_kernel(const float* __restrict__ in, __nv_bfloat16* __restrict__ out)
{
    const size_t idx = (size_t)blockIdx.x * 256 + threadIdx.x;  // float4 index
    const float4 v = reinterpret_cast<const float4*>(in)[idx];
    uint32_t w[6];
    if (ORD == 0) {
        pack_a(v, w);
    } else {
        unsigned short h[4], l[4];
        split_us(v.x, h[0], l[0]); split_us(v.y, h[1], l[1]);
        split_us(v.z, h[2], l[2]); split_us(v.w, h[3], l[3]);
        w[0] = h[0] | ((uint32_t)h[0] << 16); w[1] = l[0] | ((uint32_t)h[1] << 16);
        w[2] = h[1] | ((uint32_t)l[1] << 16); w[3] = h[2] | ((uint32_t)h[2] << 16);
        w[4] = l[2] | ((uint32_t)h[3] << 16); w[5] = h[3] | ((uint32_t)l[3] << 16);
    }
    uint2* o = reinterpret_cast<uint2*>(out + 12 * idx);
    o[0] = make_uint2(w[0], w[1]);
    o[1] = make_uint2(w[2], w[3]);
    o[2] = make_uint2(w[4], w[5]);
}

// gather unmasked context rows into compacted positions + A-triplet split
__global__ __launch_bounds__(256)
void gather_split(const float* __restrict__ context, const int* __restrict__ map,
                  const int* __restrict__ count, __nv_bfloat16* __restrict__ out)
{
    const int b = blockIdx.y, j = blockIdx.x;
    if (j >= count[b]) return;
    const int src = map[b * 2048 + j];
    const int t = threadIdx.x;
    const float4 v = reinterpret_cast<const float4*>(
        context + ((size_t)(b * 2048 + src)) * 1024)[t];
    uint32_t w[6];
    pack_a(v, w);
    uint2* o = reinterpret_cast<uint2*>(
        out + ((size_t)(b * 2048 + j)) * 3072 + 12 * (size_t)t);
    o[0] = make_uint2(w[0], w[1]);
    o[1] = make_uint2(w[2], w[3]);
    o[2] = make_uint2(w[4], w[5]);
}

// ---------------- HMMA GEMM: 128x128 tile, NT, BK=64, double-buffered ------
// EPI: 0 = plain fp32 out; 1 = bias + (hi,lo,hi) [q]; 2 = bias + (hi,hi,lo) [k]
//      3 = bias + transposed (hi,hi,lo) into vt[b][n][3m]  [v]
// MODE: 0 none; 1 exit if local-m >= count[batch(m)]; 2 exit if n0 >= count[z];
//       3 dynamic K' = 3*cpad64(count[z])  (PV)
template <int EPI, int MODE>
__global__ __launch_bounds__(256, 2)
void mm_bf16(const __nv_bfloat16* __restrict__ Ag, const __nv_bfloat16* __restrict__ Bg,
             const float* __restrict__ bias, void* __restrict__ Cg,
             const int* __restrict__ counts,
             int M, int N, int Kp, long long sA, long long sB, long long sC)
{
    extern __shared__ char sm[];
    const uint32_t sbase = smem_u32(sm);

    const int tid = threadIdx.x, wid = tid >> 5, lane = tid & 31;
    const int m0 = blockIdx.y * 128, n0 = blockIdx.x * 128;

    int KpEff = Kp;
    if (MODE == 1) { if ((m0 & 2047) >= counts[m0 >> 11]) return; }
    if (MODE == 2) { if (n0 >= counts[blockIdx.z]) return; }
    if (MODE == 3) { KpEff = 3 * ((counts[blockIdx.z] + 63) & ~63); }

    const __nv_bfloat16* A = Ag + (size_t)blockIdx.z * sA;
    const __nv_bfloat16* B = Bg + (size_t)blockIdx.z * sB;

    const int lrow = tid >> 3;      // 0..31 (+32 per step)
    const int lcol = tid & 7;       // 16B chunk

    // stage s occupies [s*32768, s*32768+16384) for A, +16384 for B
    auto load_stage = [&](int i) {
        const uint32_t abase = sbase + (i & 1) * 32768;
        const uint32_t bbase = abase + 16384;
        const int k0 = i << 6;      // bf16 elements
#pragma unroll
        for (int t = 0; t < 4; ++t) {
            const int row = lrow + t * 32;
            cp16(abase + swz(row, lcol), A + (size_t)(m0 + row) * Kp + k0 + lcol * 8);
        }
#pragma unroll
        for (int t = 0; t < 4; ++t) {
            const int row = lrow + t * 32;
            cp16(bbase + swz(row, lcol), B + (size_t)(n0 + row) * Kp + k0 + lcol * 8);
        }
        CP_COMMIT();
    };

    float acc[4][4][4];
#pragma unroll
    for (int a = 0; a < 4; ++a)
#pragma unroll
        for (int b = 0; b < 4; ++b)
#pragma unroll
            for (int c = 0; c < 4; ++c) acc[a][b][c] = 0.f;

    const int wm = wid >> 2, wn = wid & 3;     // 2 x 4 warp grid, 64x32 tiles
    const int nk = KpEff >> 6;

    load_stage(0);
    for (int i = 0; i < nk; ++i) {
        if (i + 1 < nk) { load_stage(i + 1); CP_WAIT(1); }
        else           { CP_WAIT(0); }
        __syncthreads();
        const uint32_t abase = sbase + (i & 1) * 32768;
        const uint32_t bbase = abase + 16384;
#pragma unroll
        for (int ks = 0; ks < 4; ++ks) {
            uint32_t af[4][4];
#pragma unroll
            for (int mi = 0; mi < 4; ++mi) {
                const int row = wm * 64 + mi * 16 + (lane & 15);
                const int c16 = ks * 2 + (lane >> 4);
                ldsm4(af[mi][0], af[mi][1], af[mi][2], af[mi][3], abase + swz(row, c16));
            }
            uint32_t bfr[4][2];
#pragma unroll
            for (int nb = 0; nb < 2; ++nb) {
                const int row = wn * 32 + nb * 16 + (lane & 7) + ((lane & 16) >> 1);
                const int c16 = ks * 2 + ((lane >> 3) & 1);
                uint32_t r0, r1, r2, r3;
                ldsm4(r0, r1, r2, r3, bbase + swz(row, c16));
                bfr[nb * 2][0] = r0; bfr[nb * 2][1] = r1;
                bfr[nb * 2 + 1][0] = r2; bfr[nb * 2 + 1][1] = r3;
            }
#pragma unroll
            for (int mi = 0; mi < 4; ++mi)
#pragma unroll
                for (int ni = 0; ni < 4; ++ni)
                    mma16816(acc[mi][ni], af[mi], bfr[ni][0], bfr[ni][1]);
        }
        __syncthreads();
    }

    // ---------------- epilogue ----------------
    const int l4 = lane >> 2;          // row within m8
    const int lc = (lane & 3) * 2;     // even col within n8
#pragma unroll
    for (int mi = 0; mi < 4; ++mi) {
#pragma unroll
        for (int h = 0; h < 2; ++h) {
            const int row = m0 + wm * 64 + mi * 16 + l4 + h * 8;
#pragma unroll
            for (int ni = 0; ni < 4; ++ni) {
                const int n = n0 + wn * 32 + ni * 8 + lc;
                const float v0 = acc[mi][ni][h * 2 + 0];
                const float v1 = acc[mi][ni][h * 2 + 1];
                if (EPI == 0) {
                    float* C = (float*)Cg + (size_t)blockIdx.z * sC + (size_t)row * N + n;
                    *reinterpret_cast<float2*>(C) = make_float2(v0, v1);
                } else if (EPI == 1 || EPI == 2) {
                    const float x0 = v0 + bias[n];
                    const float x1 = v1 + bias[n + 1];
                    unsigned short h0, l0, h1, l1;
                    split_us(x0, h0, l0); split_us(x1, h1, l1);
                    uint32_t w0, w1, w2;
                    if (EPI == 1) {          // (hi,lo,hi)
                        w0 = h0 | ((uint32_t)l0 << 16);
                        w1 = h0 | ((uint32_t)h1 << 16);
                        w2 = l1 | ((uint32_t)h1 << 16);
                    } else {                 // (hi,hi,lo)
                        w0 = h0 | ((uint32_t)h0 << 16);
                        w1 = l0 | ((uint32_t)h1 << 16);
                        w2 = h1 | ((uint32_t)l1 << 16);
                    }
                    uint32_t* p = reinterpret_cast<uint32_t*>(
                        (__nv_bfloat16*)Cg + (size_t)row * (size_t)(3 * N) + 3 * (size_t)n);
                    p[0] = w0; p[1] = w1; p[2] = w2;
                } else {                     // EPI==3: v transpose, (hi,hi,lo)
                    const int bb = row >> 11, mg = row & 2047;
#pragma unroll
                    for (int e = 0; e < 2; ++e) {
                        const int nn = n + e;
                        const float x = (e ? v1 : v0) + bias[nn];
                        unsigned short hh, ll;
                        split_us(x, hh, ll);
                        __nv_bfloat16* p = (__nv_bfloat16*)Cg +
                            ((size_t)(bb * 1024 + nn)) * 6144 + 3 * (size_t)mg;
                        p[0] = __ushort_as_bfloat16(hh);
                        p[1] = __ushort_as_bfloat16(hh);
                        p[2] = __ushort_as_bfloat16(ll);
                    }
                }
            }
        }
    }
}

// -------- fused scale + softmax over compacted columns + triplet split -----
__global__ __launch_bounds__(256)
void softmax_kernel(const float* __restrict__ S, const int* __restrict__ count,
                    __nv_bfloat16* __restrict__ P)
{
    const int row = blockIdx.x;          // b*2048 + n
    const int b = row >> 11;
    const int cnt = count[b];
    const int cpad = (cnt + 63) & ~63;
    const float* s = S + (size_t)row * 2048;
    const int tid = threadIdx.x;
    const float scale = 0.03125f;        // 1/sqrt(1024)

    float v[8];
    float lmax = -3.0e38f;
#pragma unroll
    for (int j = 0; j < 8; ++j) {
        const int m = tid + j * 256;
        const float x = (m < cnt) ? s[m] * scale : -3.0e38f;
        v[j] = x;
        lmax = fmaxf(lmax, x);
    }
    __shared__ float red[8];
#pragma unroll
    for (int o = 16; o; o >>= 1)
        lmax = fmaxf(lmax, __shfl_xor_sync(0xffffffffu, lmax, o));
    if ((tid & 31) == 0) red[tid >> 5] = lmax;
    __syncthreads();
    const float rmax = fmaxf(fmaxf(fmaxf(red[0], red[1]), fmaxf(red[2], red[3])),
                             fmaxf(fmaxf(red[4], red[5]), fmaxf(red[6], red[7])));
    __syncthreads();

    float lsum = 0.f;
#pragma unroll
    for (int j = 0; j < 8; ++j) { v[j] = expf(v[j] - rmax); lsum += v[j]; }
#pragma unroll
    for (int o = 16; o; o >>= 1)
        lsum += __shfl_xor_sync(0xffffffffu, lsum, o);
    if ((tid & 31) == 0) red[tid >> 5] = lsum;
    __syncthreads();
    const float inv = 1.f / (red[0] + red[1] + red[2] + red[3] +
                             red[4] + red[5] + red[6] + red[7]);

    __nv_bfloat16* op = P + (size_t)row * 6144;
#pragma unroll
    for (int j = 0; j < 8; ++j) {
        const int m = tid + j * 256;
        if (m < cnt) {
            const float p = v[j] * inv;
            unsigned short h, l;
            split_us(p, h, l);
            __nv_bfloat16* q = op + 3 * m;   // (hi,lo,hi)
            q[0] = __ushort_as_bfloat16(h);
            q[1] = __ushort_as_bfloat16(l);
            q[2] = __ushort_as_bfloat16(h);
        } else if (m < cpad) {
            __nv_bfloat16* q = op + 3 * m;
            q[0] = __ushort_as_bfloat16(0);
            q[1] = __ushort_as_bfloat16(0);
            q[2] = __ushort_as_bfloat16(0);
        }
    }
}

// ---------------- launch ----------------
static constexpr size_t SMEM_BYTES = 2 * 32768;   // 2 stages x (16KB A + 16KB B)

extern "C" void kernel_launch(void* const* d_in, const int* in_sizes, int n_in,
                              void* d_out, int out_size)
{
    const float* query   = (const float*)d_in[0];
    const float* context = (const float*)d_in[1];
    const int*   cmask   = (const int*)  d_in[2];
    const float* Wq = (const float*)d_in[3];
    const float* bq = (const float*)d_in[4];
    const float* Wk = (const float*)d_in[5];
    const float* bk = (const float*)d_in[6];
    const float* Wv = (const float*)d_in[7];
    const float* bv = (const float*)d_in[8];
    float* out = (float*)d_out;

    __nv_bfloat16 *xq, *xc, *w0, *w1, *w2, *qt, *kt, *vt, *pp;
    float* s;
    int *cnt, *map;
    cudaGetSymbolAddress((void**)&xq, g_xq);
    cudaGetSymbolAddress((void**)&xc, g_xc);
    cudaGetSymbolAddress((void**)&w0, g_w0);
    cudaGetSymbolAddress((void**)&w1, g_w1);
    cudaGetSymbolAddress((void**)&w2, g_w2);
    cudaGetSymbolAddress((void**)&qt, g_qt);
    cudaGetSymbolAddress((void**)&kt, g_kt);
    cudaGetSymbolAddress((void**)&vt, g_vt);
    cudaGetSymbolAddress((void**)&s,  g_s);
    cudaGetSymbolAddress((void**)&pp, g_p);
    cudaGetSymbolAddress((void**)&cnt, g_cnt);
    cudaGetSymbolAddress((void**)&map, g_map);

    cudaFuncSetAttribute(mm_bf16<1, 0>, cudaFuncAttributeMaxDynamicSharedMemorySize, SMEM_BYTES);
    cudaFuncSetAttribute(mm_bf16<2, 1>, cudaFuncAttributeMaxDynamicSharedMemorySize, SMEM_BYTES);
    cudaFuncSetAttribute(mm_bf16<3, 1>, cudaFuncAttributeMaxDynamicSharedMemorySize, SMEM_BYTES);
    cudaFuncSetAttribute(mm_bf16<0, 2>, cudaFuncAttributeMaxDynamicSharedMemorySize, SMEM_BYTES);
    cudaFuncSetAttribute(mm_bf16<0, 3>, cudaFuncAttributeMaxDynamicSharedMemorySize, SMEM_BYTES);

    // mask scan + compaction map
    scan_mask<<<8, 256>>>(cmask, map, cnt);

    // splits: query (A-order), weights (B-order); context gathered+compacted
    split_kernel<0><<<16384, 256>>>(query, xq);
    gather_split<<<dim3(2048, 8), 256>>>(context, map, cnt, xc);
    split_kernel<1><<<1024, 256>>>(Wq, w0);
    split_kernel<1><<<1024, 256>>>(Wk, w1);
    split_kernel<1><<<1024, 256>>>(Wv, w2);

    // projections (K'=3072): q over all rows; k,v over compacted rows
    mm_bf16<1, 0><<<dim3(8, 128, 1), 256, SMEM_BYTES>>>(xq, w0, bq, qt, nullptr,
        16384, 1024, 3072, 0, 0, 0);
    mm_bf16<2, 1><<<dim3(8, 128, 1), 256, SMEM_BYTES>>>(xc, w1, bk, kt, cnt,
        16384, 1024, 3072, 0, 0, 0);
    mm_bf16<3, 1><<<dim3(8, 128, 1), 256, SMEM_BYTES>>>(xc, w2, bv, vt, cnt,
        16384, 1024, 3072, 0, 0, 0);

    // scores: per batch [2048, count] = q' @ k'^T  (K'=3072)
    mm_bf16<0, 2><<<dim3(16, 16, 8), 256, SMEM_BYTES>>>(qt, kt, nullptr, s, cnt,
        2048, 2048, 3072, 2048ll * 3072, 2048ll * 3072, 2048ll * 2048);

    // softmax over compacted columns + prob triplet split
    softmax_kernel<<<16384, 256>>>(s, cnt, pp);

    // out: per batch [2048,1024] = P' @ vt'^T  (K' = 3*cpad64(count) dynamic)
    mm_bf16<0, 3><<<dim3(8, 16, 8), 256, SMEM_BYTES>>>(pp, vt, nullptr, out, cnt,
        2048, 1024, 6144, 2048ll * 6144, 1024ll * 6144, 2048ll * 1024);
}